// round 14
// baseline (speedup 1.0000x reference)
#include <cuda_runtime.h>
#include <cstdint>

// s1, blur: [4, 10, 256, 256] fp32 -> out: [4, 256, 256] fp32.
//
// Per pixel: candidate i (0..10): x_j = s_j + b_j (j<i) else s_j - b_j.
// argmin_i std(x, ddof=1); output mean of winner = sum_i / n.
// Scan identity: sumsq_i = const + 4 * prefixSum(s_j*b_j), so
//   argmin variance == argmin( 4*P_i - sum_i^2 / n ),
//   P_i = prefix sum s_j*b_j ; sum_i = (S-B) + 2 * prefix sum b_j.
//
// Base = plateau optimum (float2 + L2::256B granule, 512 CTAs x 256 thr,
// 6.624us). Lever: evict_last retention on input loads via the
// createpolicy + L2::cache_hint path (the bare .L2::evict_last qualifier
// is v8.b32-only on sm_103a -- r13 compile fail). The 21MB input fits 6x
// in the never-flushed 126MB L2, yet replays behave DRAM-bound; pinning
// input lines at max retention should let warm graph replays run at the
// LTS cap instead of the ~2.8 TB/s DRAM wall.

#define NPLANES 10
#define HW2     32768    // (256*256)/2 pairs per plane

__device__ __forceinline__ float2 ldg_nc_keep(const float2* p, uint64_t pol) {
    float2 r;
    asm volatile("ld.global.nc.L2::cache_hint.L2::256B.v2.f32 {%0, %1}, [%2], %3;"
                 : "=f"(r.x), "=f"(r.y) : "l"(p), "l"(pol));
    return r;
}

__global__ __launch_bounds__(256, 4)
void distregression_kernel(const float2* __restrict__ s1,
                           const float2* __restrict__ blur,
                           float2* __restrict__ out,
                           int npairs)
{
    int t = blockIdx.x * blockDim.x + threadIdx.x;
    if (t >= npairs) return;

    // Max-retention (evict_last, fraction 1.0) access policy for inputs.
    uint64_t pol;
    asm volatile("createpolicy.fractional.L2::evict_last.b64 %0, 1.0;" : "=l"(pol));

    int b   = t >> 15;            // pair / HW2 -> batch
    int hw2 = t & (HW2 - 1);

    const float2* s1p = s1   + (size_t)b * NPLANES * HW2 + hw2;
    const float2* blp = blur + (size_t)b * NPLANES * HW2 + hw2;

    // Front-batch all 20 vector loads (MLP=20, 256B granule, evict_last).
    float sv[NPLANES][2], bv[NPLANES][2];
    #pragma unroll
    for (int j = 0; j < NPLANES; j++) {
        float2 s = ldg_nc_keep(s1p + j * HW2, pol);
        float2 v = ldg_nc_keep(blp + j * HW2, pol);
        sv[j][0] = s.x; sv[j][1] = s.y;
        bv[j][0] = v.x; bv[j][1] = v.y;
    }

    const float inv_n = 1.0f / NPLANES;
    float res[2];
    #pragma unroll
    for (int k = 0; k < 2; k++) {
        float S = 0.f, B = 0.f;
        #pragma unroll
        for (int j = 0; j < NPLANES; j++) {
            S += sv[j][k];
            B += bv[j][k];
        }

        float sum = S - B;      // candidate 0: all lo
        float P   = 0.f;        // prefix sum of s_j*b_j
        float bestM = 3.0e38f, bestSum = sum;

        #pragma unroll
        for (int i = 0; i <= NPLANES; i++) {
            float M = fmaf(-sum * inv_n, sum, 4.0f * P);
            if (M < bestM) { bestM = M; bestSum = sum; }   // first index wins ties
            if (i < NPLANES) {
                sum = fmaf(2.0f, bv[i][k], sum);
                P   = fmaf(sv[i][k], bv[i][k], P);
            }
        }
        res[k] = bestSum * inv_n;
    }

    out[t] = make_float2(res[0], res[1]);
}

extern "C" void kernel_launch(void* const* d_in, const int* in_sizes, int n_in,
                              void* d_out, int out_size)
{
    const float2* s1   = (const float2*)d_in[0];
    const float2* blur = (const float2*)d_in[1];
    float2* out = (float2*)d_out;

    int npairs  = out_size / 2;                      // 131072
    int threads = 256;
    int blocks  = (npairs + threads - 1) / threads;  // 512
    distregression_kernel<<<blocks, threads>>>(s1, blur, out, npairs);
}

// round 15
// speedup vs baseline: 1.0337x; 1.0337x over previous
#include <cuda_runtime.h>
#include <cstdint>

// s1, blur: [4, 10, 256, 256] fp32 -> out: [4, 256, 256] fp32.
//
// Per pixel: candidate i (0..10): x_j = s_j + b_j (j<i) else s_j - b_j.
// argmin_i std(x, ddof=1); output mean of winner = sum_i / n.
// Scan identity: sumsq_i = const + 4 * prefixSum(s_j*b_j), so
//   argmin variance == argmin( 4*P_i - sum_i^2 / n ),
//   P_i = prefix sum s_j*b_j ; sum_i = (S-B) + 2 * prefix sum b_j.
//
// FINAL — measured optimum over 14 rounds / 12 designs:
//   * float2 loads + L2::256B fetch granule (warp span per plane = 256B =
//     granule): best timed (6.624us, reached twice with this exact config)
//     AND best cold profile (7.23us, 2.90 TB/s).
//   * 512 CTAs x 256 threads, ~34% occ, 53 regs.
//   * plain default-policy stores (.cs measured worse, r10) and no
//     createpolicy hint (evict_last measured no better, r14).
// Falsified levers: FP64 comparator (66us, FP64 pipe), occupancy 13-67%,
// LDG width 32/64/128, TMA bulk, persistent cp.async pipeline, grid
// balance, streaming stores, L2 eviction priority. All correct designs sit
// on a 6.62-6.91us plateau (run noise +/-0.3us) = the platform floor for
// this 22MB-traffic kernel at the ~2.8-3.3 TB/s short-kernel DRAM wall.

#define NPLANES 10
#define HW2     32768    // (256*256)/2 pairs per plane

__device__ __forceinline__ float2 ldg_nc_256(const float2* p) {
    float2 r;
    asm volatile("ld.global.nc.L2::256B.v2.f32 {%0, %1}, [%2];"
                 : "=f"(r.x), "=f"(r.y) : "l"(p));
    return r;
}

__global__ __launch_bounds__(256, 4)
void distregression_kernel(const float2* __restrict__ s1,
                           const float2* __restrict__ blur,
                           float2* __restrict__ out,
                           int npairs)
{
    int t = blockIdx.x * blockDim.x + threadIdx.x;
    if (t >= npairs) return;

    int b   = t >> 15;            // pair / HW2 -> batch
    int hw2 = t & (HW2 - 1);

    const float2* s1p = s1   + (size_t)b * NPLANES * HW2 + hw2;
    const float2* blp = blur + (size_t)b * NPLANES * HW2 + hw2;

    // Front-batch all 20 vector loads (MLP=20, 256B L2 fetch granule).
    float sv[NPLANES][2], bv[NPLANES][2];
    #pragma unroll
    for (int j = 0; j < NPLANES; j++) {
        float2 s = ldg_nc_256(s1p + j * HW2);
        float2 v = ldg_nc_256(blp + j * HW2);
        sv[j][0] = s.x; sv[j][1] = s.y;
        bv[j][0] = v.x; bv[j][1] = v.y;
    }

    const float inv_n = 1.0f / NPLANES;
    float res[2];
    #pragma unroll
    for (int k = 0; k < 2; k++) {
        float S = 0.f, B = 0.f;
        #pragma unroll
        for (int j = 0; j < NPLANES; j++) {
            S += sv[j][k];
            B += bv[j][k];
        }

        float sum = S - B;      // candidate 0: all lo
        float P   = 0.f;        // prefix sum of s_j*b_j
        float bestM = 3.0e38f, bestSum = sum;

        #pragma unroll
        for (int i = 0; i <= NPLANES; i++) {
            float M = fmaf(-sum * inv_n, sum, 4.0f * P);
            if (M < bestM) { bestM = M; bestSum = sum; }   // first index wins ties
            if (i < NPLANES) {
                sum = fmaf(2.0f, bv[i][k], sum);
                P   = fmaf(sv[i][k], bv[i][k], P);
            }
        }
        res[k] = bestSum * inv_n;
    }

    out[t] = make_float2(res[0], res[1]);
}

extern "C" void kernel_launch(void* const* d_in, const int* in_sizes, int n_in,
                              void* d_out, int out_size)
{
    const float2* s1   = (const float2*)d_in[0];
    const float2* blur = (const float2*)d_in[1];
    float2* out = (float2*)d_out;

    int npairs  = out_size / 2;                      // 131072
    int threads = 256;
    int blocks  = (npairs + threads - 1) / threads;  // 512
    distregression_kernel<<<blocks, threads>>>(s1, blur, out, npairs);
}

// round 16
// speedup vs baseline: 1.0437x; 1.0097x over previous
#include <cuda_runtime.h>
#include <cstdint>

// s1, blur: [4, 10, 256, 256] fp32 -> out: [4, 256, 256] fp32.
//
// Per pixel: candidate i (0..10): x_j = s_j + b_j (j<i) else s_j - b_j.
// argmin_i std(x, ddof=1); output mean of winner = sum_i / n.
// Scan identity: sumsq_i = const + 4 * prefixSum(s_j*b_j), so
//   argmin variance == argmin( 4*P_i - sum_i^2 / n ),
//   P_i = prefix sum s_j*b_j ; sum_i = (S-B) + 2 * prefix sum b_j.
//
// FINAL — measured optimum over 15 rounds / 12 designs:
//   * float2 loads + L2::256B fetch granule (warp span per plane = 256B =
//     fetch granule). Timed distribution of this exact config:
//     {6.624, 6.624, 6.656} us — best and tightest of any design; also the
//     best cold profile (7.23-7.39us, 2.84-2.90 TB/s).
//   * 512 CTAs x 256 threads, ~36% occ, 53 regs.
//   * default-policy stores (.cs measured worse, r10); no createpolicy
//     retention hint (measured no better, r14).
// Falsified levers: FP64 comparator (66us — B300 FP64 pipe), LDG width
// 32/64/128, TMA bulk, persistent cp.async pipeline, occupancy 13-67%,
// grid balance, streaming stores, L2 eviction priority, cross-replay L2
// residency. All correct designs sit on a 6.62-6.91us plateau (replay
// noise +/-0.3us) = platform floor for 22MB of traffic at the ~2.8-3.3
// TB/s short-kernel DRAM wall.

#define NPLANES 10
#define HW2     32768    // (256*256)/2 pairs per plane

__device__ __forceinline__ float2 ldg_nc_256(const float2* p) {
    float2 r;
    asm volatile("ld.global.nc.L2::256B.v2.f32 {%0, %1}, [%2];"
                 : "=f"(r.x), "=f"(r.y) : "l"(p));
    return r;
}

__global__ __launch_bounds__(256, 4)
void distregression_kernel(const float2* __restrict__ s1,
                           const float2* __restrict__ blur,
                           float2* __restrict__ out,
                           int npairs)
{
    int t = blockIdx.x * blockDim.x + threadIdx.x;
    if (t >= npairs) return;

    int b   = t >> 15;            // pair / HW2 -> batch
    int hw2 = t & (HW2 - 1);

    const float2* s1p = s1   + (size_t)b * NPLANES * HW2 + hw2;
    const float2* blp = blur + (size_t)b * NPLANES * HW2 + hw2;

    // Front-batch all 20 vector loads (MLP=20, 256B L2 fetch granule).
    float sv[NPLANES][2], bv[NPLANES][2];
    #pragma unroll
    for (int j = 0; j < NPLANES; j++) {
        float2 s = ldg_nc_256(s1p + j * HW2);
        float2 v = ldg_nc_256(blp + j * HW2);
        sv[j][0] = s.x; sv[j][1] = s.y;
        bv[j][0] = v.x; bv[j][1] = v.y;
    }

    const float inv_n = 1.0f / NPLANES;
    float res[2];
    #pragma unroll
    for (int k = 0; k < 2; k++) {
        float S = 0.f, B = 0.f;
        #pragma unroll
        for (int j = 0; j < NPLANES; j++) {
            S += sv[j][k];
            B += bv[j][k];
        }

        float sum = S - B;      // candidate 0: all lo
        float P   = 0.f;        // prefix sum of s_j*b_j
        float bestM = 3.0e38f, bestSum = sum;

        #pragma unroll
        for (int i = 0; i <= NPLANES; i++) {
            float M = fmaf(-sum * inv_n, sum, 4.0f * P);
            if (M < bestM) { bestM = M; bestSum = sum; }   // first index wins ties
            if (i < NPLANES) {
                sum = fmaf(2.0f, bv[i][k], sum);
                P   = fmaf(sv[i][k], bv[i][k], P);
            }
        }
        res[k] = bestSum * inv_n;
    }

    out[t] = make_float2(res[0], res[1]);
}

extern "C" void kernel_launch(void* const* d_in, const int* in_sizes, int n_in,
                              void* d_out, int out_size)
{
    const float2* s1   = (const float2*)d_in[0];
    const float2* blur = (const float2*)d_in[1];
    float2* out = (float2*)d_out;

    int npairs  = out_size / 2;                      // 131072
    int threads = 256;
    int blocks  = (npairs + threads - 1) / threads;  // 512
    distregression_kernel<<<blocks, threads>>>(s1, blur, out, npairs);
}